// round 5
// baseline (speedup 1.0000x reference)
#include <cuda_runtime.h>
#include <cstdint>

// Problem constants
#define B_    4
#define N_    2048
#define DIM_  1024
#define H_    16
#define D_    64
#define SCALE_ 0.125f   // HEAD_DIM^-0.5 = 1/8, exact in fp32

// ---------------------------------------------------------------------------
// Scratch (device globals: allocation-free)
//   g_q/g_k/g_v: [B, H, N, D]   g_o: [B, N, DIM]  (attention out, pre-proj)
// ---------------------------------------------------------------------------
__device__ __align__(16) float g_q[B_ * H_ * N_ * D_];
__device__ __align__(16) float g_k[B_ * H_ * N_ * D_];
__device__ __align__(16) float g_v[B_ * H_ * N_ * D_];
__device__ __align__(16) float g_o[(size_t)B_ * N_ * DIM_];

// ---------------------------------------------------------------------------
// Helpers
// ---------------------------------------------------------------------------
__device__ __forceinline__ uint32_t f2tf(float f) {
    uint32_t r;
    asm("cvt.rna.tf32.f32 %0, %1;" : "=r"(r) : "f"(f));
    return r;
}

__device__ __forceinline__ void mma_tf32(float c[4],
                                         uint32_t a0, uint32_t a1, uint32_t a2, uint32_t a3,
                                         uint32_t b0, uint32_t b1) {
    asm volatile(
        "mma.sync.aligned.m16n8k8.row.col.f32.tf32.tf32.f32 "
        "{%0,%1,%2,%3}, {%4,%5,%6,%7}, {%8,%9}, {%0,%1,%2,%3};\n"
        : "+f"(c[0]), "+f"(c[1]), "+f"(c[2]), "+f"(c[3])
        : "r"(a0), "r"(a1), "r"(a2), "r"(a3), "r"(b0), "r"(b1));
}

__device__ __forceinline__ void cp16(float* dst_smem, const float* src_gmem) {
    uint32_t s = (uint32_t)__cvta_generic_to_shared(dst_smem);
    asm volatile("cp.async.cg.shared.global [%0], [%1], 16;\n" :: "r"(s), "l"(src_gmem));
}
__device__ __forceinline__ void cp_commit() {
    asm volatile("cp.async.commit_group;\n" ::: "memory");
}
__device__ __forceinline__ void cp_wait0() {
    asm volatile("cp.async.wait_group 0;\n" ::: "memory");
}

// ---------------------------------------------------------------------------
// Generic 128x128 (BK=32) tf32 GEMM mainloop.
//   8 warps as 2(m) x 4(n); warp tile 64x32 -> 4x4 m16n8 accum tiles.
//   Smem strides: A 36 (banks (4r+c)%32 conflict-free), B 136 ((8k+n)%32 CF).
//   Double-buffered cp.async, 1 group in flight.
// ---------------------------------------------------------------------------
#define SA_STRIDE 36
#define SB_STRIDE 136
#define SA_SZ (128 * SA_STRIDE)   // 4608 floats
#define SB_SZ (32 * SB_STRIDE)    // 4352 floats
#define GEMM_SMEM_FLOATS (2 * (SA_SZ + SB_SZ))   // 17920 floats = 71680 B

__device__ __forceinline__ void gemm_issue(float* sA, float* sB,
                                           const float* Ag, int lda,
                                           const float* Bg, int ldb, int tid) {
#pragma unroll
    for (int i = 0; i < 4; i++) {
        int idx = tid + i * 256;
        int r  = idx >> 3, c4 = (idx & 7) << 2;          // A: 128 rows x 32 cols
        cp16(sA + r * SA_STRIDE + c4, Ag + (size_t)r * lda + c4);
        int rb = idx >> 5, cb = (idx & 31) << 2;         // B: 32 rows x 128 cols
        cp16(sB + rb * SB_STRIDE + cb, Bg + (size_t)rb * ldb + cb);
    }
    cp_commit();
}

__device__ __forceinline__ void gemm_tf32_128x128(const float* __restrict__ A, int lda,
                                                  const float* __restrict__ Bm, int ldb,
                                                  int bm, int bn, int K,
                                                  float c[4][4][4], float* smem) {
    const int tid  = threadIdx.x;
    const int lane = tid & 31, warp = tid >> 5;
    const int wm = warp >> 2, wn = warp & 3;     // 2 x 4 warp grid
    const int g = lane >> 2, tg = lane & 3;

    float* sAb[2] = { smem,                       smem + SA_SZ + SB_SZ };
    float* sBb[2] = { smem + SA_SZ,               smem + 2 * SA_SZ + SB_SZ };

    const int KT = K >> 5;
    const float* Abase = A + (size_t)bm * 128 * lda;
    const float* Bbase = Bm + bn * 128;

    gemm_issue(sAb[0], sBb[0], Abase, lda, Bbase, ldb, tid);

    for (int kt = 0; kt < KT; kt++) {
        cp_wait0();
        __syncthreads();
        if (kt + 1 < KT)
            gemm_issue(sAb[(kt + 1) & 1], sBb[(kt + 1) & 1],
                       Abase + (kt + 1) * 32, lda,
                       Bbase + (size_t)(kt + 1) * 32 * ldb, ldb, tid);

        const float* a = sAb[kt & 1];
        const float* b = sBb[kt & 1];
#pragma unroll
        for (int ks = 0; ks < 4; ks++) {
            uint32_t af[4][4], bf[4][2];
            const int cc = ks * 8 + tg;
#pragma unroll
            for (int mt = 0; mt < 4; mt++) {
                int r = wm * 64 + mt * 16 + g;
                af[mt][0] = f2tf(a[r * SA_STRIDE + cc]);
                af[mt][1] = f2tf(a[(r + 8) * SA_STRIDE + cc]);
                af[mt][2] = f2tf(a[r * SA_STRIDE + cc + 4]);
                af[mt][3] = f2tf(a[(r + 8) * SA_STRIDE + cc + 4]);
            }
            const int kr = ks * 8 + tg;
#pragma unroll
            for (int nt = 0; nt < 4; nt++) {
                int cn = wn * 32 + nt * 8 + g;
                bf[nt][0] = f2tf(b[kr * SB_STRIDE + cn]);
                bf[nt][1] = f2tf(b[(kr + 4) * SB_STRIDE + cn]);
            }
#pragma unroll
            for (int mt = 0; mt < 4; mt++)
#pragma unroll
                for (int nt = 0; nt < 4; nt++)
                    mma_tf32(c[mt][nt], af[mt][0], af[mt][1], af[mt][2], af[mt][3],
                             bf[nt][0], bf[nt][1]);
        }
        // next iteration's top sync protects the buffer being recycled
    }
}

// ---------------------------------------------------------------------------
// Kernel 1: QKV GEMM, scatter epilogue into q/k/v [B,H,N,D]
// X:[8192,1024] @ Wqkv:[1024,3072]
// ---------------------------------------------------------------------------
__device__ __forceinline__ void qkv_scatter(int m, int n, float v0, float v1) {
    int b = m >> 11, seq = m & 2047;
    int sel = n >> 10, rem = n & 1023;
    int h = rem >> 6, d = rem & 63;
    float* base = (sel == 0) ? g_q : (sel == 1) ? g_k : g_v;
    *(float2*)&base[(((size_t)(b * H_ + h)) * N_ + seq) * D_ + d] = make_float2(v0, v1);
}

__global__ __launch_bounds__(256, 2)
void qkv_gemm_kernel(const float* __restrict__ X, const float* __restrict__ W) {
    extern __shared__ float smem[];
    const int lane = threadIdx.x & 31, warp = threadIdx.x >> 5;
    const int wm = warp >> 2, wn = warp & 3;
    const int g = lane >> 2, tg = lane & 3;

    float c[4][4][4];
#pragma unroll
    for (int i = 0; i < 4; i++)
#pragma unroll
        for (int j = 0; j < 4; j++)
#pragma unroll
            for (int k = 0; k < 4; k++) c[i][j][k] = 0.f;

    gemm_tf32_128x128(X, DIM_, W, 3 * DIM_, blockIdx.y, blockIdx.x, DIM_, c, smem);

#pragma unroll
    for (int mt = 0; mt < 4; mt++)
#pragma unroll
        for (int nt = 0; nt < 4; nt++) {
            int m = blockIdx.y * 128 + wm * 64 + mt * 16 + g;
            int n = blockIdx.x * 128 + wn * 32 + nt * 8 + (tg << 1);
            qkv_scatter(m,     n, c[mt][nt][0], c[mt][nt][1]);
            qkv_scatter(m + 8, n, c[mt][nt][2], c[mt][nt][3]);
        }
}

// ---------------------------------------------------------------------------
// Kernel 2: flash attention per (b,h). Br=Bc=128, D=64, online softmax.
//   smem: sK [128][68], sV [128][72], sP [128][132]  (all strides conflict-free)
//   8 warps; warp w owns query rows 16w..16w+15.
// ---------------------------------------------------------------------------
#define SK_STRIDE 68
#define SV_STRIDE 72
#define SP_STRIDE 132
#define FLASH_SMEM_FLOATS (128 * (SK_STRIDE + SV_STRIDE + SP_STRIDE))   // 34816 = 139264 B

__global__ __launch_bounds__(256, 1)
void flash_attn_kernel() {
    extern __shared__ float smem[];
    float* sK = smem;
    float* sV = sK + 128 * SK_STRIDE;
    float* sP = sV + 128 * SV_STRIDE;

    const int tid = threadIdx.x, lane = tid & 31, warp = tid >> 5;
    const int g = lane >> 2, tg = lane & 3;
    const int w16 = warp * 16;
    const int bh = blockIdx.y, qb = blockIdx.x;

    const float* Qp = g_q + (size_t)bh * N_ * D_;
    const float* Kp = g_k + (size_t)bh * N_ * D_;
    const float* Vp = g_v + (size_t)bh * N_ * D_;

    // Stage Q tile into sP (reused later as P), then pull per-warp A fragments.
    for (int idx = tid; idx < 2048; idx += 256) {
        int r = idx >> 4, c4 = (idx & 15) << 2;
        *(float4*)&sP[r * SP_STRIDE + c4] =
            *(const float4*)&Qp[(size_t)(qb * 128 + r) * D_ + c4];
    }
    __syncthreads();

    uint32_t qf[8][4];
#pragma unroll
    for (int ks = 0; ks < 8; ks++) {
        int r = w16 + g, cc = ks * 8 + tg;
        qf[ks][0] = f2tf(sP[r * SP_STRIDE + cc] * SCALE_);
        qf[ks][1] = f2tf(sP[(r + 8) * SP_STRIDE + cc] * SCALE_);
        qf[ks][2] = f2tf(sP[r * SP_STRIDE + cc + 4] * SCALE_);
        qf[ks][3] = f2tf(sP[(r + 8) * SP_STRIDE + cc + 4] * SCALE_);
    }
    // (warp w only ever reads/writes sP rows 16w..16w+15 from here on)

    float m0 = -1e30f, m1 = -1e30f, l0 = 0.f, l1 = 0.f;
    float o[8][4];
#pragma unroll
    for (int i = 0; i < 8; i++)
#pragma unroll
        for (int j = 0; j < 4; j++) o[i][j] = 0.f;

    for (int kb = 0; kb < 16; kb++) {
        __syncthreads();   // protect sK/sV reuse
        for (int idx = tid; idx < 2048; idx += 256) {
            int r = idx >> 4, c4 = (idx & 15) << 2;
            *(float4*)&sK[r * SK_STRIDE + c4] =
                *(const float4*)&Kp[(size_t)(kb * 128 + r) * D_ + c4];
            *(float4*)&sV[r * SV_STRIDE + c4] =
                *(const float4*)&Vp[(size_t)(kb * 128 + r) * D_ + c4];
        }
        __syncthreads();

        // S = (Q*scale) @ K^T   (16 query rows x 128 keys per warp)
        float s[16][4];
#pragma unroll
        for (int i = 0; i < 16; i++)
#pragma unroll
            for (int j = 0; j < 4; j++) s[i][j] = 0.f;

#pragma unroll
        for (int ks = 0; ks < 8; ks++) {
            const int kr = ks * 8 + tg;
#pragma unroll
            for (int nt = 0; nt < 16; nt++) {
                int kc = nt * 8 + g;
                uint32_t b0 = f2tf(sK[kc * SK_STRIDE + kr]);
                uint32_t b1 = f2tf(sK[kc * SK_STRIDE + kr + 4]);
                mma_tf32(s[nt], qf[ks][0], qf[ks][1], qf[ks][2], qf[ks][3], b0, b1);
            }
        }

        // Online softmax (rows r0 = w16+g, r1 = r0+8)
        float rm0 = -1e30f, rm1 = -1e30f;
#pragma unroll
        for (int nt = 0; nt < 16; nt++) {
            rm0 = fmaxf(rm0, fmaxf(s[nt][0], s[nt][1]));
            rm1 = fmaxf(rm1, fmaxf(s[nt][2], s[nt][3]));
        }
        rm0 = fmaxf(rm0, __shfl_xor_sync(0xffffffffu, rm0, 1));
        rm0 = fmaxf(rm0, __shfl_xor_sync(0xffffffffu, rm0, 2));
        rm1 = fmaxf(rm1, __shfl_xor_sync(0xffffffffu, rm1, 1));
        rm1 = fmaxf(rm1, __shfl_xor_sync(0xffffffffu, rm1, 2));

        float mn0 = fmaxf(m0, rm0), mn1 = fmaxf(m1, rm1);
        float al0 = __expf(m0 - mn0), al1 = __expf(m1 - mn1);

        float rs0 = 0.f, rs1 = 0.f;
#pragma unroll
        for (int nt = 0; nt < 16; nt++) {
            float p0 = __expf(s[nt][0] - mn0);
            float p1 = __expf(s[nt][1] - mn0);
            float p2 = __expf(s[nt][2] - mn1);
            float p3 = __expf(s[nt][3] - mn1);
            rs0 += p0 + p1;
            rs1 += p2 + p3;
            *(float2*)&sP[(w16 + g) * SP_STRIDE + nt * 8 + (tg << 1)]     = make_float2(p0, p1);
            *(float2*)&sP[(w16 + g + 8) * SP_STRIDE + nt * 8 + (tg << 1)] = make_float2(p2, p3);
        }
        rs0 += __shfl_xor_sync(0xffffffffu, rs0, 1);
        rs0 += __shfl_xor_sync(0xffffffffu, rs0, 2);
        rs1 += __shfl_xor_sync(0xffffffffu, rs1, 1);
        rs1 += __shfl_xor_sync(0xffffffffu, rs1, 2);

        l0 = l0 * al0 + rs0;
        l1 = l1 * al1 + rs1;
        m0 = mn0; m1 = mn1;

#pragma unroll
        for (int dt = 0; dt < 8; dt++) {
            o[dt][0] *= al0; o[dt][1] *= al0;
            o[dt][2] *= al1; o[dt][3] *= al1;
        }
        __syncwarp();

        // O += P @ V
#pragma unroll
        for (int ks2 = 0; ks2 < 16; ks2++) {
            int r = w16 + g, cc = ks2 * 8 + tg;
            uint32_t a0 = f2tf(sP[r * SP_STRIDE + cc]);
            uint32_t a1 = f2tf(sP[(r + 8) * SP_STRIDE + cc]);
            uint32_t a2 = f2tf(sP[r * SP_STRIDE + cc + 4]);
            uint32_t a3 = f2tf(sP[(r + 8) * SP_STRIDE + cc + 4]);
            const int kr = ks2 * 8 + tg;
#pragma unroll
            for (int dt = 0; dt < 8; dt++) {
                int dc = dt * 8 + g;
                uint32_t b0 = f2tf(sV[kr * SV_STRIDE + dc]);
                uint32_t b1 = f2tf(sV[(kr + 4) * SV_STRIDE + dc]);
                mma_tf32(o[dt], a0, a1, a2, a3, b0, b1);
            }
        }
    }

    // Epilogue: O /= l, write [B,N,DIM] with d-offset h*64
    const float il0 = 1.f / l0, il1 = 1.f / l1;
    const int b = bh >> 4, h = bh & 15;
    const int q0 = qb * 128 + w16 + g;
    float* Ob0 = g_o + ((size_t)b * N_ + q0) * DIM_ + h * 64;
    float* Ob1 = g_o + ((size_t)b * N_ + q0 + 8) * DIM_ + h * 64;
#pragma unroll
    for (int dt = 0; dt < 8; dt++) {
        int d = dt * 8 + (tg << 1);
        *(float2*)&Ob0[d] = make_float2(o[dt][0] * il0, o[dt][1] * il0);
        *(float2*)&Ob1[d] = make_float2(o[dt][2] * il1, o[dt][3] * il1);
    }
}

// ---------------------------------------------------------------------------
// Kernel 3: output projection  g_o[8192,1024] @ Wproj[1024,1024] + b
// ---------------------------------------------------------------------------
__global__ __launch_bounds__(256, 2)
void proj_gemm_kernel(const float* __restrict__ W, const float* __restrict__ bias,
                      float* __restrict__ out) {
    extern __shared__ float smem[];
    const int lane = threadIdx.x & 31, warp = threadIdx.x >> 5;
    const int wm = warp >> 2, wn = warp & 3;
    const int g = lane >> 2, tg = lane & 3;

    float c[4][4][4];
#pragma unroll
    for (int i = 0; i < 4; i++)
#pragma unroll
        for (int j = 0; j < 4; j++)
#pragma unroll
            for (int k = 0; k < 4; k++) c[i][j][k] = 0.f;

    gemm_tf32_128x128(g_o, DIM_, W, DIM_, blockIdx.y, blockIdx.x, DIM_, c, smem);

#pragma unroll
    for (int mt = 0; mt < 4; mt++)
#pragma unroll
        for (int nt = 0; nt < 4; nt++) {
            int m = blockIdx.y * 128 + wm * 64 + mt * 16 + g;
            int n = blockIdx.x * 128 + wn * 32 + nt * 8 + (tg << 1);
            float2 bb = *(const float2*)&bias[n];
            *(float2*)&out[(size_t)m * DIM_ + n] =
                make_float2(c[mt][nt][0] + bb.x, c[mt][nt][1] + bb.y);
            *(float2*)&out[(size_t)(m + 8) * DIM_ + n] =
                make_float2(c[mt][nt][2] + bb.x, c[mt][nt][3] + bb.y);
        }
}

// ---------------------------------------------------------------------------
// Launch
// ---------------------------------------------------------------------------
extern "C" void kernel_launch(void* const* d_in, const int* in_sizes, int n_in,
                              void* d_out, int out_size) {
    const float* x     = (const float*)d_in[0];
    const float* Wqkv  = (const float*)d_in[1];
    const float* Wproj = (const float*)d_in[2];
    const float* bproj = (const float*)d_in[3];
    float* out = (float*)d_out;

    const int GEMM_SMEM  = GEMM_SMEM_FLOATS * 4;    // 71680 B
    const int FLASH_SMEM = FLASH_SMEM_FLOATS * 4;   // 139264 B

    cudaFuncSetAttribute(qkv_gemm_kernel,  cudaFuncAttributeMaxDynamicSharedMemorySize, GEMM_SMEM);
    cudaFuncSetAttribute(proj_gemm_kernel, cudaFuncAttributeMaxDynamicSharedMemorySize, GEMM_SMEM);
    cudaFuncSetAttribute(flash_attn_kernel, cudaFuncAttributeMaxDynamicSharedMemorySize, FLASH_SMEM);

    // 1) QKV projection + scatter to [B,H,N,D]
    qkv_gemm_kernel<<<dim3(24, 64), 256, GEMM_SMEM>>>(x, Wqkv);
    // 2) flash attention per (b,h)
    flash_attn_kernel<<<dim3(16, 64), 256, FLASH_SMEM>>>();
    // 3) output projection + bias
    proj_gemm_kernel<<<dim3(8, 64), 256, GEMM_SMEM>>>(Wproj, bproj, out);
}

// round 7
// speedup vs baseline: 1.2302x; 1.2302x over previous
#include <cuda_runtime.h>
#include <cstdint>

// Problem constants
#define B_    4
#define N_    2048
#define DIM_  1024
#define H_    16
#define D_    64

// ---------------------------------------------------------------------------
// Scratch (device globals: allocation-free)
//   g_xc   : X pre-converted to tf32, columns pair-permuted within 8-groups
//   g_wqkvc/g_wprojc : weights pre-converted to tf32 (natural layout)
//   g_q/g_k: [B,H,N,D] tf32, d pair-permuted (q pre-scaled by 0.125)
//   g_v    : [B,H,N,D] tf32, natural d
//   g_o    : [B,N,DIM] tf32, columns pair-permuted (proj A operand)
// ---------------------------------------------------------------------------
__device__ __align__(16) float g_xc[(size_t)B_ * N_ * DIM_];
__device__ __align__(16) float g_wqkvc[(size_t)DIM_ * 3 * DIM_];
__device__ __align__(16) float g_wprojc[(size_t)DIM_ * DIM_];
__device__ __align__(16) float g_q[B_ * H_ * N_ * D_];
__device__ __align__(16) float g_k[B_ * H_ * N_ * D_];
__device__ __align__(16) float g_v[B_ * H_ * N_ * D_];
__device__ __align__(16) float g_o[(size_t)B_ * N_ * DIM_];

// ---------------------------------------------------------------------------
// Helpers
// ---------------------------------------------------------------------------
__device__ __forceinline__ uint32_t f2tf(float f) {
    uint32_t r;
    asm("cvt.rna.tf32.f32 %0, %1;" : "=r"(r) : "f"(f));
    return r;
}
__device__ __forceinline__ float f2tff(float f) { return __uint_as_float(f2tf(f)); }
__device__ __forceinline__ uint32_t asu(float f) { return __float_as_uint(f); }

// forward perm: value for k stored at column q(k); pairs (k, k+4) -> (2k', 2k'+1)
__device__ __forceinline__ int qperm(int j) { return ((j & 3) << 1) | (j >> 2); }
// inverse: column c holds value for k = p(c)
__device__ __forceinline__ int pperm(int c) { return ((c & 1) << 2) | (c >> 1); }

__device__ __forceinline__ void mma_tf32(float c[4],
                                         uint32_t a0, uint32_t a1, uint32_t a2, uint32_t a3,
                                         uint32_t b0, uint32_t b1) {
    asm volatile(
        "mma.sync.aligned.m16n8k8.row.col.f32.tf32.tf32.f32 "
        "{%0,%1,%2,%3}, {%4,%5,%6,%7}, {%8,%9}, {%0,%1,%2,%3};\n"
        : "+f"(c[0]), "+f"(c[1]), "+f"(c[2]), "+f"(c[3])
        : "r"(a0), "r"(a1), "r"(a2), "r"(a3), "r"(b0), "r"(b1));
}

__device__ __forceinline__ void cp16(float* dst_smem, const float* src_gmem) {
    uint32_t s = (uint32_t)__cvta_generic_to_shared(dst_smem);
    asm volatile("cp.async.cg.shared.global [%0], [%1], 16;\n" :: "r"(s), "l"(src_gmem));
}
__device__ __forceinline__ void cp_commit() {
    asm volatile("cp.async.commit_group;\n" ::: "memory");
}
__device__ __forceinline__ void cp_wait0() {
    asm volatile("cp.async.wait_group 0;\n" ::: "memory");
}

// ---------------------------------------------------------------------------
// Conversion kernels (one-time, memory-bound)
// ---------------------------------------------------------------------------
__global__ void cvt_copy_kernel(const float* __restrict__ src, float* __restrict__ dst, int n) {
    for (int i = blockIdx.x * blockDim.x + threadIdx.x; i < n; i += gridDim.x * blockDim.x)
        dst[i] = f2tff(src[i]);
}
// A-side: tf32 + pair-permute columns within 8-groups (row length multiple of 8)
__global__ void cvt_permA_kernel(const float* __restrict__ src, float* __restrict__ dst, int n) {
    for (int i = blockIdx.x * blockDim.x + threadIdx.x; i < n; i += gridDim.x * blockDim.x)
        dst[i] = f2tff(src[(i & ~7) | pperm(i & 7)]);
}

// ---------------------------------------------------------------------------
// Generic 128x128 (BK=32) tf32 GEMM mainloop, pre-converted operands.
//   A smem stride 40 (LDS.64 pairs, conflict-free per half-warp phase)
//   B smem stride 136 (scalar loads, perfectly conflict-free)
// ---------------------------------------------------------------------------
#define SA_STRIDE 40
#define SB_STRIDE 136
#define SA_SZ (128 * SA_STRIDE)   // 5120 floats
#define SB_SZ (32 * SB_STRIDE)    // 4352 floats
#define GEMM_SMEM_FLOATS (2 * (SA_SZ + SB_SZ))   // 18944 floats = 75776 B

__device__ __forceinline__ void gemm_issue(float* sA, float* sB,
                                           const float* Ag, int lda,
                                           const float* Bg, int ldb, int tid) {
#pragma unroll
    for (int i = 0; i < 4; i++) {
        int idx = tid + i * 256;
        int r  = idx >> 3, c4 = (idx & 7) << 2;          // A: 128 rows x 32 cols
        cp16(sA + r * SA_STRIDE + c4, Ag + (size_t)r * lda + c4);
        int rb = idx >> 5, cb = (idx & 31) << 2;         // B: 32 rows x 128 cols
        cp16(sB + rb * SB_STRIDE + cb, Bg + (size_t)rb * ldb + cb);
    }
    cp_commit();
}

__device__ __forceinline__ void gemm_tf32_128x128(const float* __restrict__ A, int lda,
                                                  const float* __restrict__ Bm, int ldb,
                                                  int bm, int bn, int K,
                                                  float c[4][4][4], float* smem) {
    const int tid  = threadIdx.x;
    const int lane = tid & 31, warp = tid >> 5;
    const int wm = warp >> 2, wn = warp & 3;     // 2 x 4 warp grid
    const int g = lane >> 2, tg = lane & 3;

    float* sAb[2] = { smem,             smem + SA_SZ + SB_SZ };
    float* sBb[2] = { smem + SA_SZ,     smem + 2 * SA_SZ + SB_SZ };

    const int KT = K >> 5;
    const float* Abase = A + (size_t)bm * 128 * lda;
    const float* Bbase = Bm + bn * 128;

    gemm_issue(sAb[0], sBb[0], Abase, lda, Bbase, ldb, tid);

    for (int kt = 0; kt < KT; kt++) {
        cp_wait0();
        __syncthreads();
        if (kt + 1 < KT)
            gemm_issue(sAb[(kt + 1) & 1], sBb[(kt + 1) & 1],
                       Abase + (kt + 1) * 32, lda,
                       Bbase + (size_t)(kt + 1) * 32 * ldb, ldb, tid);

        const float* a = sAb[kt & 1];
        const float* b = sBb[kt & 1];
#pragma unroll
        for (int ks = 0; ks < 4; ks++) {
            uint32_t af[4][4], bf[4][2];
            const int cc2 = ks * 8 + (tg << 1);   // permuted pair (k, k+4)
#pragma unroll
            for (int mt = 0; mt < 4; mt++) {
                int r = wm * 64 + mt * 16 + g;
                float2 a01 = *(const float2*)&a[r * SA_STRIDE + cc2];
                float2 a23 = *(const float2*)&a[(r + 8) * SA_STRIDE + cc2];
                af[mt][0] = asu(a01.x); af[mt][2] = asu(a01.y);
                af[mt][1] = asu(a23.x); af[mt][3] = asu(a23.y);
            }
            const int kr = ks * 8 + tg;
#pragma unroll
            for (int nt = 0; nt < 4; nt++) {
                int cn = wn * 32 + nt * 8 + g;
                bf[nt][0] = asu(b[kr * SB_STRIDE + cn]);
                bf[nt][1] = asu(b[(kr + 4) * SB_STRIDE + cn]);
            }
#pragma unroll
            for (int mt = 0; mt < 4; mt++)
#pragma unroll
                for (int nt = 0; nt < 4; nt++)
                    mma_tf32(c[mt][nt], af[mt][0], af[mt][1], af[mt][2], af[mt][3],
                             bf[nt][0], bf[nt][1]);
        }
    }
}

// ---------------------------------------------------------------------------
// Kernel 1: QKV GEMM, tf32 epilogue scatter into q/k/v [B,H,N,D]
//   q: *0.125 (exact), d pair-permuted   k: d pair-permuted   v: natural
// ---------------------------------------------------------------------------
__device__ __forceinline__ void qkv_scatter(int m, int n, float v0, float v1) {
    int b = m >> 11, seq = m & 2047;
    int sel = n >> 10, rem = n & 1023;
    int h = rem >> 6, d = rem & 63;
    size_t off = (((size_t)(b * H_ + h)) * N_ + seq) * D_;
    if (sel == 2) {
        *(float2*)&g_v[off + d] = make_float2(f2tff(v0), f2tff(v1));
    } else {
        float* base = sel ? g_k : g_q;
        float s = sel ? 1.0f : 0.125f;
        int d0 = (d & ~7) | qperm(d & 7);
        int d1 = (d & ~7) | qperm((d & 7) + 1);
        base[off + d0] = f2tff(v0 * s);
        base[off + d1] = f2tff(v1 * s);
    }
}

__global__ __launch_bounds__(256, 2)
void qkv_gemm_kernel(const float* __restrict__ X, const float* __restrict__ W) {
    extern __shared__ float smem[];
    const int lane = threadIdx.x & 31, warp = threadIdx.x >> 5;
    const int wm = warp >> 2, wn = warp & 3;
    const int g = lane >> 2, tg = lane & 3;

    float c[4][4][4];
#pragma unroll
    for (int i = 0; i < 4; i++)
#pragma unroll
        for (int j = 0; j < 4; j++)
#pragma unroll
            for (int k = 0; k < 4; k++) c[i][j][k] = 0.f;

    gemm_tf32_128x128(X, DIM_, W, 3 * DIM_, blockIdx.y, blockIdx.x, DIM_, c, smem);

#pragma unroll
    for (int mt = 0; mt < 4; mt++)
#pragma unroll
        for (int nt = 0; nt < 4; nt++) {
            int m = blockIdx.y * 128 + wm * 64 + mt * 16 + g;
            int n = blockIdx.x * 128 + wn * 32 + nt * 8 + (tg << 1);
            qkv_scatter(m,     n, c[mt][nt][0], c[mt][nt][1]);
            qkv_scatter(m + 8, n, c[mt][nt][2], c[mt][nt][3]);
        }
}

// ---------------------------------------------------------------------------
// Kernel 2: flash attention per (b,h). Br=128, Bc=64, online softmax.
//   All operands pre-tf32. cp.async double-buffered K/V.
//   smem: sK[2][64*72], sV[2][64*72], sP[128*68]  -> 108544 B -> occupancy 2
// ---------------------------------------------------------------------------
#define SK_STRIDE 72
#define SV_STRIDE 72
#define SP_STRIDE 68
#define KV_SZ (64 * SK_STRIDE)              // 4608 floats per buffer
#define FLASH_SMEM_FLOATS (4 * KV_SZ + 128 * SP_STRIDE)   // 27136 = 108544 B

__device__ __forceinline__ void flash_issue(float* sKb, float* sVb,
                                            const float* Kg, const float* Vg, int tid) {
#pragma unroll
    for (int i = 0; i < 4; i++) {
        int idx = tid + i * 256;                 // 0..1023
        int r = idx >> 4, c4 = (idx & 15) << 2;  // 64 rows x 64 cols
        cp16(sKb + r * SK_STRIDE + c4, Kg + r * 64 + c4);
        cp16(sVb + r * SV_STRIDE + c4, Vg + r * 64 + c4);
    }
    cp_commit();
}

__global__ __launch_bounds__(256, 2)
void flash_attn_kernel() {
    extern __shared__ float smem[];
    float* sKb[2] = { smem,              smem + KV_SZ };
    float* sVb[2] = { smem + 2 * KV_SZ,  smem + 3 * KV_SZ };
    float* sP = smem + 4 * KV_SZ;

    const int tid = threadIdx.x, lane = tid & 31, warp = tid >> 5;
    const int g = lane >> 2, tg = lane & 3;
    const int w16 = warp * 16;
    const int bh = blockIdx.y, qb = blockIdx.x;

    const float* Qp = g_q + (size_t)bh * N_ * D_;
    const float* Kp = g_k + (size_t)bh * N_ * D_;
    const float* Vp = g_v + (size_t)bh * N_ * D_;

    // kick off first K/V tile load
    flash_issue(sKb[0], sVb[0], Kp, Vp, tid);

    // Stage Q tile into sP (raw tf32, pre-scaled, d pair-permuted)
    for (int idx = tid; idx < 2048; idx += 256) {
        int r = idx >> 4, c4 = (idx & 15) << 2;
        *(float4*)&sP[r * SP_STRIDE + c4] =
            *(const float4*)&Qp[(size_t)(qb * 128 + r) * D_ + c4];
    }
    __syncthreads();

    uint32_t qf[8][4];
#pragma unroll
    for (int ks = 0; ks < 8; ks++) {
        int r = w16 + g, cc2 = ks * 8 + (tg << 1);
        float2 x0 = *(const float2*)&sP[r * SP_STRIDE + cc2];
        float2 x1 = *(const float2*)&sP[(r + 8) * SP_STRIDE + cc2];
        qf[ks][0] = asu(x0.x); qf[ks][2] = asu(x0.y);
        qf[ks][1] = asu(x1.x); qf[ks][3] = asu(x1.y);
    }
    // (warp w only touches sP rows 16w..16w+15 from here on)

    float m0 = -1e30f, m1 = -1e30f, l0 = 0.f, l1 = 0.f;
    float o[8][4];
#pragma unroll
    for (int i = 0; i < 8; i++)
#pragma unroll
        for (int j = 0; j < 4; j++) o[i][j] = 0.f;

    for (int kb = 0; kb < 32; kb++) {
        cp_wait0();
        __syncthreads();
        if (kb + 1 < 32)
            flash_issue(sKb[(kb + 1) & 1], sVb[(kb + 1) & 1],
                        Kp + (kb + 1) * 64 * 64, Vp + (kb + 1) * 64 * 64, tid);

        const float* sK = sKb[kb & 1];
        const float* sV = sVb[kb & 1];

        // S = Qs @ K^T   (16 query rows x 64 keys per warp)
        float s[8][4];
#pragma unroll
        for (int i = 0; i < 8; i++)
#pragma unroll
            for (int j = 0; j < 4; j++) s[i][j] = 0.f;

#pragma unroll
        for (int ks = 0; ks < 8; ks++) {
            const int kr2 = ks * 8 + (tg << 1);   // permuted d-pair
#pragma unroll
            for (int nt = 0; nt < 8; nt++) {
                int kc = nt * 8 + g;
                float2 bb = *(const float2*)&sK[kc * SK_STRIDE + kr2];
                mma_tf32(s[nt], qf[ks][0], qf[ks][1], qf[ks][2], qf[ks][3],
                         asu(bb.x), asu(bb.y));
            }
        }

        // Online softmax (rows r0 = w16+g, r1 = r0+8)
        float rm0 = -1e30f, rm1 = -1e30f;
#pragma unroll
        for (int nt = 0; nt < 8; nt++) {
            rm0 = fmaxf(rm0, fmaxf(s[nt][0], s[nt][1]));
            rm1 = fmaxf(rm1, fmaxf(s[nt][2], s[nt][3]));
        }
        rm0 = fmaxf(rm0, __shfl_xor_sync(0xffffffffu, rm0, 1));
        rm0 = fmaxf(rm0, __shfl_xor_sync(0xffffffffu, rm0, 2));
        rm1 = fmaxf(rm1, __shfl_xor_sync(0xffffffffu, rm1, 1));
        rm1 = fmaxf(rm1, __shfl_xor_sync(0xffffffffu, rm1, 2));

        float mn0 = fmaxf(m0, rm0), mn1 = fmaxf(m1, rm1);
        float al0 = __expf(m0 - mn0), al1 = __expf(m1 - mn1);

        float rs0 = 0.f, rs1 = 0.f;
#pragma unroll
        for (int nt = 0; nt < 8; nt++) {
            float p0 = __expf(s[nt][0] - mn0);
            float p1 = __expf(s[nt][1] - mn0);
            float p2 = __expf(s[nt][2] - mn1);
            float p3 = __expf(s[nt][3] - mn1);
            rs0 += p0 + p1;
            rs1 += p2 + p3;
            *(float2*)&sP[(w16 + g) * SP_STRIDE + nt * 8 + (tg << 1)] =
                make_float2(f2tff(p0), f2tff(p1));
            *(float2*)&sP[(w16 + g + 8) * SP_STRIDE + nt * 8 + (tg << 1)] =
                make_float2(f2tff(p2), f2tff(p3));
        }
        rs0 += __shfl_xor_sync(0xffffffffu, rs0, 1);
        rs0 += __shfl_xor_sync(0xffffffffu, rs0, 2);
        rs1 += __shfl_xor_sync(0xffffffffu, rs1, 1);
        rs1 += __shfl_xor_sync(0xffffffffu, rs1, 2);

        l0 = l0 * al0 + rs0;
        l1 = l1 * al1 + rs1;
        m0 = mn0; m1 = mn1;

#pragma unroll
        for (int dt = 0; dt < 8; dt++) {
            o[dt][0] *= al0; o[dt][1] *= al0;
            o[dt][2] *= al1; o[dt][3] *= al1;
        }
        __syncwarp();

        // O += P @ V
#pragma unroll
        for (int ks2 = 0; ks2 < 8; ks2++) {
            int r = w16 + g, cc = ks2 * 8 + tg;
            uint32_t a0 = asu(sP[r * SP_STRIDE + cc]);
            uint32_t a1 = asu(sP[(r + 8) * SP_STRIDE + cc]);
            uint32_t a2 = asu(sP[r * SP_STRIDE + cc + 4]);
            uint32_t a3 = asu(sP[(r + 8) * SP_STRIDE + cc + 4]);
            const int kr = ks2 * 8 + tg;
#pragma unroll
            for (int dt = 0; dt < 8; dt++) {
                int dc = dt * 8 + g;
                uint32_t b0 = asu(sV[kr * SV_STRIDE + dc]);
                uint32_t b1 = asu(sV[(kr + 4) * SV_STRIDE + dc]);
                mma_tf32(o[dt], a0, a1, a2, a3, b0, b1);
            }
        }
    }

    // Epilogue: O /= l, tf32, d pair-permute (g_o feeds proj GEMM A side)
    const float il0 = 1.f / l0, il1 = 1.f / l1;
    const int b = bh >> 4, h = bh & 15;
    const int q0 = qb * 128 + w16 + g;
    float* Ob0 = g_o + ((size_t)b * N_ + q0) * DIM_ + h * 64;
    float* Ob1 = g_o + ((size_t)b * N_ + q0 + 8) * DIM_ + h * 64;
    const int j0 = qperm(tg << 1), j1 = qperm((tg << 1) + 1);
#pragma unroll
    for (int dt = 0; dt < 8; dt++) {
        Ob0[dt * 8 + j0] = f2tff(o[dt][0] * il0);
        Ob0[dt * 8 + j1] = f2tff(o[dt][1] * il0);
        Ob1[dt * 8 + j0] = f2tff(o[dt][2] * il1);
        Ob1[dt * 8 + j1] = f2tff(o[dt][3] * il1);
    }
}

// ---------------------------------------------------------------------------
// Kernel 3: output projection  g_o[8192,1024](tf32,perm) @ Wproj_c + bias
// ---------------------------------------------------------------------------
__global__ __launch_bounds__(256, 2)
void proj_gemm_kernel(const float* __restrict__ W, const float* __restrict__ bias,
                      float* __restrict__ out) {
    extern __shared__ float smem[];
    const int lane = threadIdx.x & 31, warp = threadIdx.x >> 5;
    const int wm = warp >> 2, wn = warp & 3;
    const int g = lane >> 2, tg = lane & 3;

    float c[4][4][4];
#pragma unroll
    for (int i = 0; i < 4; i++)
#pragma unroll
        for (int j = 0; j < 4; j++)
#pragma unroll
            for (int k = 0; k < 4; k++) c[i][j][k] = 0.f;

    gemm_tf32_128x128(g_o, DIM_, W, DIM_, blockIdx.y, blockIdx.x, DIM_, c, smem);

#pragma unroll
    for (int mt = 0; mt < 4; mt++)
#pragma unroll
        for (int nt = 0; nt < 4; nt++) {
            int m = blockIdx.y * 128 + wm * 64 + mt * 16 + g;
            int n = blockIdx.x * 128 + wn * 32 + nt * 8 + (tg << 1);
            float2 bb = *(const float2*)&bias[n];
            *(float2*)&out[(size_t)m * DIM_ + n] =
                make_float2(c[mt][nt][0] + bb.x, c[mt][nt][1] + bb.y);
            *(float2*)&out[(size_t)(m + 8) * DIM_ + n] =
                make_float2(c[mt][nt][2] + bb.x, c[mt][nt][3] + bb.y);
        }
}

// ---------------------------------------------------------------------------
// Launch
// ---------------------------------------------------------------------------
extern "C" void kernel_launch(void* const* d_in, const int* in_sizes, int n_in,
                              void* d_out, int out_size) {
    const float* x     = (const float*)d_in[0];
    const float* Wqkv  = (const float*)d_in[1];
    const float* Wproj = (const float*)d_in[2];
    const float* bproj = (const float*)d_in[3];
    float* out = (float*)d_out;

    const int GEMM_SMEM  = GEMM_SMEM_FLOATS * 4;    // 75776 B
    const int FLASH_SMEM = FLASH_SMEM_FLOATS * 4;   // 108544 B

    cudaFuncSetAttribute(qkv_gemm_kernel,   cudaFuncAttributeMaxDynamicSharedMemorySize, GEMM_SMEM);
    cudaFuncSetAttribute(proj_gemm_kernel,  cudaFuncAttributeMaxDynamicSharedMemorySize, GEMM_SMEM);
    cudaFuncSetAttribute(flash_attn_kernel, cudaFuncAttributeMaxDynamicSharedMemorySize, FLASH_SMEM);

    float* g_xc_p;    cudaGetSymbolAddress((void**)&g_xc_p,    g_xc);
    float* g_wqkv_p;  cudaGetSymbolAddress((void**)&g_wqkv_p,  g_wqkvc);
    float* g_wproj_p; cudaGetSymbolAddress((void**)&g_wproj_p, g_wprojc);

    // 0) one-time tf32 conversions (A-side also pair-permuted)
    cvt_permA_kernel<<<4096, 256>>>(x,     g_xc_p,    B_ * N_ * DIM_);
    cvt_copy_kernel <<<2048, 256>>>(Wqkv,  g_wqkv_p,  DIM_ * 3 * DIM_);
    cvt_copy_kernel <<<1024, 256>>>(Wproj, g_wproj_p, DIM_ * DIM_);
    // 1) QKV projection + tf32 scatter to [B,H,N,D]
    qkv_gemm_kernel<<<dim3(24, 64), 256, GEMM_SMEM>>>(g_xc_p, g_wqkv_p);
    // 2) flash attention per (b,h)
    flash_attn_kernel<<<dim3(16, 64), 256, FLASH_SMEM>>>();
    // 3) output projection + bias
    proj_gemm_kernel<<<dim3(8, 64), 256, GEMM_SMEM>>>(g_wproj_p, bproj, out);
}

// round 8
// speedup vs baseline: 1.3379x; 1.0876x over previous
#include <cuda_runtime.h>
#include <cstdint>

// Problem constants
#define B_    4
#define N_    2048
#define DIM_  1024
#define H_    16
#define D_    64
#define QSCALE_ (0.125f * 1.4426950408889634f)   // head_dim^-0.5 * log2(e)

// ---------------------------------------------------------------------------
// Scratch (device globals: allocation-free)
//   g_xc    : X tf32, k pair-permuted within 8-groups           [8192,1024]
//   g_wqkvt : Wqkv^T tf32, k pair-permuted                      [3072,1024]
//   g_wprojt: Wproj^T tf32, k pair-permuted                     [1024,1024]
//   g_q/g_k : [B,H,N,D] tf32, d pair-permuted (q pre-scaled by 0.125*log2e)
//   g_v     : [B,H,N,D] tf32 natural
//   g_vt    : [B,H,D,N] tf32, n pair-permuted (flash PV B operand)
//   g_o     : [B,N,DIM] tf32, columns pair-permuted (proj A operand)
// ---------------------------------------------------------------------------
__device__ __align__(16) float g_xc[(size_t)B_ * N_ * DIM_];
__device__ __align__(16) float g_wqkvt[(size_t)3 * DIM_ * DIM_];
__device__ __align__(16) float g_wprojt[(size_t)DIM_ * DIM_];
__device__ __align__(16) float g_q[B_ * H_ * N_ * D_];
__device__ __align__(16) float g_k[B_ * H_ * N_ * D_];
__device__ __align__(16) float g_v[B_ * H_ * N_ * D_];
__device__ __align__(16) float g_vt[B_ * H_ * N_ * D_];
__device__ __align__(16) float g_o[(size_t)B_ * N_ * DIM_];

// ---------------------------------------------------------------------------
// Helpers
// ---------------------------------------------------------------------------
__device__ __forceinline__ uint32_t f2tf(float f) {
    uint32_t r;
    asm("cvt.rna.tf32.f32 %0, %1;" : "=r"(r) : "f"(f));
    return r;
}
__device__ __forceinline__ float f2tff(float f) { return __uint_as_float(f2tf(f)); }
__device__ __forceinline__ uint32_t asu(float f) { return __float_as_uint(f); }
__device__ __forceinline__ float ex2(float x) {
    float r;
    asm("ex2.approx.f32 %0, %1;" : "=f"(r) : "f"(x));
    return r;
}

// forward perm: value for k stored at column q(k); pairs (k, k+4) -> (2k', 2k'+1)
__device__ __forceinline__ int qperm(int j) { return ((j & 3) << 1) | (j >> 2); }
// inverse: column c holds value for k = p(c)
__device__ __forceinline__ int pperm(int c) { return ((c & 1) << 2) | (c >> 1); }

__device__ __forceinline__ void mma_tf32(float c[4],
                                         uint32_t a0, uint32_t a1, uint32_t a2, uint32_t a3,
                                         uint32_t b0, uint32_t b1) {
    asm volatile(
        "mma.sync.aligned.m16n8k8.row.col.f32.tf32.tf32.f32 "
        "{%0,%1,%2,%3}, {%4,%5,%6,%7}, {%8,%9}, {%0,%1,%2,%3};\n"
        : "+f"(c[0]), "+f"(c[1]), "+f"(c[2]), "+f"(c[3])
        : "r"(a0), "r"(a1), "r"(a2), "r"(a3), "r"(b0), "r"(b1));
}

__device__ __forceinline__ void cp16(float* dst_smem, const float* src_gmem) {
    uint32_t s = (uint32_t)__cvta_generic_to_shared(dst_smem);
    asm volatile("cp.async.cg.shared.global [%0], [%1], 16;\n" :: "r"(s), "l"(src_gmem));
}
__device__ __forceinline__ void cp_commit() {
    asm volatile("cp.async.commit_group;\n" ::: "memory");
}
__device__ __forceinline__ void cp_wait0() {
    asm volatile("cp.async.wait_group 0;\n" ::: "memory");
}

// ---------------------------------------------------------------------------
// One-time conversion kernels (memory-bound)
// ---------------------------------------------------------------------------
// A-side: tf32 + pair-permute columns within 8-groups
__global__ void cvt_permA_kernel(const float* __restrict__ src, float* __restrict__ dst, int n) {
    for (int i = blockIdx.x * blockDim.x + threadIdx.x; i < n; i += gridDim.x * blockDim.x)
        dst[i] = f2tff(src[(i & ~7) | pperm(i & 7)]);
}

// B-side: transpose W[K][Nc] -> Wt[Nc][K], tf32, k pair-permuted within 8-groups
__global__ void cvt_transB_kernel(const float* __restrict__ src, float* __restrict__ dst,
                                  int K, int Nc) {
    __shared__ float t[32][33];
    const int n0 = blockIdx.x * 32, k0 = blockIdx.y * 32;
    const int tx = threadIdx.x, ty = threadIdx.y;
#pragma unroll
    for (int i = ty; i < 32; i += 8)
        t[i][tx] = src[(size_t)(k0 + i) * Nc + n0 + tx];
    __syncthreads();
    const int kc = (tx & ~7) | qperm(tx & 7);
#pragma unroll
    for (int i = ty; i < 32; i += 8)
        dst[(size_t)(n0 + i) * K + k0 + kc] = f2tff(t[tx][i]);
}

// V transpose: g_v[bh][N][D] -> g_vt[bh][D][N], n pair-permuted (already tf32)
__global__ void vtrans_kernel() {
    __shared__ float t[32][33];
    const int bh = blockIdx.z;
    const int n0 = blockIdx.x * 32, d0 = blockIdx.y * 32;
    const float* src = g_v + ((size_t)bh * N_ + n0) * D_ + d0;
    float* dst = g_vt + ((size_t)bh * D_ + d0) * N_ + n0;
    const int tx = threadIdx.x, ty = threadIdx.y;
#pragma unroll
    for (int i = ty; i < 32; i += 8)
        t[i][tx] = src[(size_t)i * D_ + tx];
    __syncthreads();
    const int nc = (tx & ~7) | qperm(tx & 7);
#pragma unroll
    for (int i = ty; i < 32; i += 8)
        dst[(size_t)i * N_ + nc] = t[tx][i];
}

// ---------------------------------------------------------------------------
// Generic 128x128 (BK=32) tf32 GEMM mainloop; BOTH operands k-contiguous,
// pair-permuted within 8-groups -> all fragment loads are LDS.64.
//   A: rows m, lda along k.  Bt: rows n, ldb along k.
//   smem stride 40 for both (banks (8r + 2tg) conflict-free per phase).
// ---------------------------------------------------------------------------
#define S_STRIDE 40
#define TILE_SZ (128 * S_STRIDE)                 // 5120 floats
#define GEMM_SMEM_FLOATS (4 * TILE_SZ)           // 20480 floats = 81920 B

__device__ __forceinline__ void gemm_issue(float* sA, float* sB,
                                           const float* Ag, int lda,
                                           const float* Bg, int ldb, int tid) {
#pragma unroll
    for (int i = 0; i < 4; i++) {
        int idx = tid + i * 256;
        int r = idx >> 3, c4 = (idx & 7) << 2;   // 128 rows x 32 cols each
        cp16(sA + r * S_STRIDE + c4, Ag + (size_t)r * lda + c4);
        cp16(sB + r * S_STRIDE + c4, Bg + (size_t)r * ldb + c4);
    }
    cp_commit();
}

__device__ __forceinline__ void gemm_tf32_128x128(const float* __restrict__ A, int lda,
                                                  const float* __restrict__ Bt, int ldb,
                                                  int bm, int bn, int K,
                                                  float c[4][4][4], float* smem) {
    const int tid  = threadIdx.x;
    const int lane = tid & 31, warp = tid >> 5;
    const int wm = warp >> 2, wn = warp & 3;     // 2 x 4 warp grid
    const int g = lane >> 2, tg = lane & 3;

    float* sAb[2] = { smem,               smem + 2 * TILE_SZ };
    float* sBb[2] = { smem + TILE_SZ,     smem + 3 * TILE_SZ };

    const int KT = K >> 5;
    const float* Abase = A  + (size_t)bm * 128 * lda;
    const float* Bbase = Bt + (size_t)bn * 128 * ldb;

    gemm_issue(sAb[0], sBb[0], Abase, lda, Bbase, ldb, tid);

    for (int kt = 0; kt < KT; kt++) {
        cp_wait0();
        __syncthreads();
        if (kt + 1 < KT)
            gemm_issue(sAb[(kt + 1) & 1], sBb[(kt + 1) & 1],
                       Abase + (kt + 1) * 32, lda,
                       Bbase + (kt + 1) * 32, ldb, tid);

        const float* a = sAb[kt & 1];
        const float* b = sBb[kt & 1];
#pragma unroll
        for (int ks = 0; ks < 4; ks++) {
            uint32_t af[4][4], bf[4][2];
            const int cc2 = ks * 8 + (tg << 1);   // permuted pair (k, k+4)
#pragma unroll
            for (int mt = 0; mt < 4; mt++) {
                int r = wm * 64 + mt * 16 + g;
                float2 a01 = *(const float2*)&a[r * S_STRIDE + cc2];
                float2 a23 = *(const float2*)&a[(r + 8) * S_STRIDE + cc2];
                af[mt][0] = asu(a01.x); af[mt][2] = asu(a01.y);
                af[mt][1] = asu(a23.x); af[mt][3] = asu(a23.y);
            }
#pragma unroll
            for (int nt = 0; nt < 4; nt++) {
                int cn = wn * 32 + nt * 8 + g;
                float2 bb = *(const float2*)&b[cn * S_STRIDE + cc2];
                bf[nt][0] = asu(bb.x); bf[nt][1] = asu(bb.y);
            }
#pragma unroll
            for (int mt = 0; mt < 4; mt++)
#pragma unroll
                for (int nt = 0; nt < 4; nt++)
                    mma_tf32(c[mt][nt], af[mt][0], af[mt][1], af[mt][2], af[mt][3],
                             bf[nt][0], bf[nt][1]);
        }
    }
}

// ---------------------------------------------------------------------------
// Kernel 1: QKV GEMM, tf32 epilogue scatter into q/k/v [B,H,N,D]
//   q: * 0.125*log2e, d pair-permuted   k: d pair-permuted   v: natural
// ---------------------------------------------------------------------------
__device__ __forceinline__ void qkv_scatter(int m, int n, float v0, float v1) {
    int b = m >> 11, seq = m & 2047;
    int sel = n >> 10, rem = n & 1023;
    int h = rem >> 6, d = rem & 63;
    size_t off = (((size_t)(b * H_ + h)) * N_ + seq) * D_;
    if (sel == 2) {
        *(float2*)&g_v[off + d] = make_float2(f2tff(v0), f2tff(v1));
    } else {
        float* base = sel ? g_k : g_q;
        float s = sel ? 1.0f : QSCALE_;
        int d0 = (d & ~7) | qperm(d & 7);
        int d1 = (d & ~7) | qperm((d & 7) + 1);
        base[off + d0] = f2tff(v0 * s);
        base[off + d1] = f2tff(v1 * s);
    }
}

__global__ __launch_bounds__(256, 2)
void qkv_gemm_kernel(const float* __restrict__ X, const float* __restrict__ Wt) {
    extern __shared__ float smem[];
    const int lane = threadIdx.x & 31, warp = threadIdx.x >> 5;
    const int wm = warp >> 2, wn = warp & 3;
    const int g = lane >> 2, tg = lane & 3;

    float c[4][4][4];
#pragma unroll
    for (int i = 0; i < 4; i++)
#pragma unroll
        for (int j = 0; j < 4; j++)
#pragma unroll
            for (int k = 0; k < 4; k++) c[i][j][k] = 0.f;

    gemm_tf32_128x128(X, DIM_, Wt, DIM_, blockIdx.y, blockIdx.x, DIM_, c, smem);

#pragma unroll
    for (int mt = 0; mt < 4; mt++)
#pragma unroll
        for (int nt = 0; nt < 4; nt++) {
            int m = blockIdx.y * 128 + wm * 64 + mt * 16 + g;
            int n = blockIdx.x * 128 + wn * 32 + nt * 8 + (tg << 1);
            qkv_scatter(m,     n, c[mt][nt][0], c[mt][nt][1]);
            qkv_scatter(m + 8, n, c[mt][nt][2], c[mt][nt][3]);
        }
}

// ---------------------------------------------------------------------------
// Kernel 2: flash attention per (b,h). Br=128, Bc=64, log2-domain softmax.
//   K tile [64 seq][64 d(perm)], Vt tile [64 d][64 seq(perm)], both LDS.64.
//   cp.async double-buffered. smem 108544 B -> 2 CTAs/SM (reg-limited too).
// ---------------------------------------------------------------------------
#define SK_STRIDE 72
#define SVT_STRIDE 72
#define SP_STRIDE 68
#define KV_SZ (64 * SK_STRIDE)              // 4608 floats per buffer
#define FLASH_SMEM_FLOATS (4 * KV_SZ + 128 * SP_STRIDE)   // 27136 = 108544 B

__device__ __forceinline__ void flash_issue(float* sKb, float* sVtb,
                                            const float* Kg, const float* Vtg, int tid) {
#pragma unroll
    for (int i = 0; i < 4; i++) {
        int idx = tid + i * 256;                 // 0..1023
        int r = idx >> 4, c4 = (idx & 15) << 2;  // 64 rows x 64 cols
        cp16(sKb  + r * SK_STRIDE  + c4, Kg  + r * 64 + c4);
        cp16(sVtb + r * SVT_STRIDE + c4, Vtg + (size_t)r * N_ + c4);
    }
    cp_commit();
}

__global__ __launch_bounds__(256, 2)
void flash_attn_kernel() {
    extern __shared__ float smem[];
    float* sKb[2]  = { smem,              smem + KV_SZ };
    float* sVtb[2] = { smem + 2 * KV_SZ,  smem + 3 * KV_SZ };
    float* sP = smem + 4 * KV_SZ;

    const int tid = threadIdx.x, lane = tid & 31, warp = tid >> 5;
    const int g = lane >> 2, tg = lane & 3;
    const int w16 = warp * 16;
    const int bh = blockIdx.y, qb = blockIdx.x;

    const float* Qp  = g_q  + (size_t)bh * N_ * D_;
    const float* Kp  = g_k  + (size_t)bh * N_ * D_;
    const float* Vtp = g_vt + (size_t)bh * D_ * N_;

    // kick off first K/Vt tile load
    flash_issue(sKb[0], sVtb[0], Kp, Vtp, tid);

    // Stage Q tile into sP (tf32, pre-scaled by 0.125*log2e, d pair-permuted)
    for (int idx = tid; idx < 2048; idx += 256) {
        int r = idx >> 4, c4 = (idx & 15) << 2;
        *(float4*)&sP[r * SP_STRIDE + c4] =
            *(const float4*)&Qp[(size_t)(qb * 128 + r) * D_ + c4];
    }
    __syncthreads();

    uint32_t qf[8][4];
#pragma unroll
    for (int ks = 0; ks < 8; ks++) {
        int r = w16 + g, cc2 = ks * 8 + (tg << 1);
        float2 x0 = *(const float2*)&sP[r * SP_STRIDE + cc2];
        float2 x1 = *(const float2*)&sP[(r + 8) * SP_STRIDE + cc2];
        qf[ks][0] = asu(x0.x); qf[ks][2] = asu(x0.y);
        qf[ks][1] = asu(x1.x); qf[ks][3] = asu(x1.y);
    }
    // (warp w only touches sP rows 16w..16w+15 from here on)

    float m0 = -1e30f, m1 = -1e30f, l0 = 0.f, l1 = 0.f;
    float o[8][4];
#pragma unroll
    for (int i = 0; i < 8; i++)
#pragma unroll
        for (int j = 0; j < 4; j++) o[i][j] = 0.f;

    for (int kb = 0; kb < 32; kb++) {
        cp_wait0();
        __syncthreads();
        if (kb + 1 < 32)
            flash_issue(sKb[(kb + 1) & 1], sVtb[(kb + 1) & 1],
                        Kp + (kb + 1) * 64 * 64, Vtp + (kb + 1) * 64, tid);

        const float* sK  = sKb[kb & 1];
        const float* sVt = sVtb[kb & 1];

        // S = Qs @ K^T   (16 query rows x 64 keys per warp), log2 domain
        float s[8][4];
#pragma unroll
        for (int i = 0; i < 8; i++)
#pragma unroll
            for (int j = 0; j < 4; j++) s[i][j] = 0.f;

#pragma unroll
        for (int ks = 0; ks < 8; ks++) {
            const int kr2 = ks * 8 + (tg << 1);   // permuted d-pair
#pragma unroll
            for (int nt = 0; nt < 8; nt++) {
                int kc = nt * 8 + g;
                float2 bb = *(const float2*)&sK[kc * SK_STRIDE + kr2];
                mma_tf32(s[nt], qf[ks][0], qf[ks][1], qf[ks][2], qf[ks][3],
                         asu(bb.x), asu(bb.y));
            }
        }

        // Online softmax in log2 domain (rows r0 = w16+g, r1 = r0+8)
        float rm0 = -1e30f, rm1 = -1e30f;
#pragma unroll
        for (int nt = 0; nt < 8; nt++) {
            rm0 = fmaxf(rm0, fmaxf(s[nt][0], s[nt][1]));
            rm1 = fmaxf(rm1, fmaxf(s[nt][2], s[nt][3]));
        }
        rm0 = fmaxf(rm0, __shfl_xor_sync(0xffffffffu, rm0, 1));
        rm0 = fmaxf(rm0, __shfl_xor_sync(0xffffffffu, rm0, 2));
        rm1 = fmaxf(rm1, __shfl_xor_sync(0xffffffffu, rm1, 1));
        rm1 = fmaxf(rm1, __shfl_xor_sync(0xffffffffu, rm1, 2));

        float mn0 = fmaxf(m0, rm0), mn1 = fmaxf(m1, rm1);
        float al0 = ex2(m0 - mn0), al1 = ex2(m1 - mn1);

        float rs0 = 0.f, rs1 = 0.f;
#pragma unroll
        for (int nt = 0; nt < 8; nt++) {
            float p0 = ex2(s[nt][0] - mn0);
            float p1 = ex2(s[nt][1] - mn0);
            float p2 = ex2(s[nt][2] - mn1);
            float p3 = ex2(s[nt][3] - mn1);
            rs0 += p0 + p1;
            rs1 += p2 + p3;
            *(float2*)&sP[(w16 + g) * SP_STRIDE + nt * 8 + (tg << 1)] =
                make_float2(f2tff(p0), f2tff(p1));
            *(float2*)&sP[(w16 + g + 8) * SP_STRIDE + nt * 8 + (tg << 1)] =
                make_float2(f2tff(p2), f2tff(p3));
        }
        rs0 += __shfl_xor_sync(0xffffffffu, rs0, 1);
        rs0 += __shfl_xor_sync(0xffffffffu, rs0, 2);
        rs1 += __shfl_xor_sync(0xffffffffu, rs1, 1);
        rs1 += __shfl_xor_sync(0xffffffffu, rs1, 2);

        l0 = l0 * al0 + rs0;
        l1 = l1 * al1 + rs1;
        m0 = mn0; m1 = mn1;

#pragma unroll
        for (int dt = 0; dt < 8; dt++) {
            o[dt][0] *= al0; o[dt][1] *= al0;
            o[dt][2] *= al1; o[dt][3] *= al1;
        }
        __syncwarp();

        // O += P @ V   (Vt tile: row d, cols seq pair-permuted -> LDS.64)
#pragma unroll
        for (int ks2 = 0; ks2 < 8; ks2++) {
            int r = w16 + g, cc = ks2 * 8 + tg;
            uint32_t a0 = asu(sP[r * SP_STRIDE + cc]);
            uint32_t a1 = asu(sP[(r + 8) * SP_STRIDE + cc]);
            uint32_t a2 = asu(sP[r * SP_STRIDE + cc + 4]);
            uint32_t a3 = asu(sP[(r + 8) * SP_STRIDE + cc + 4]);
            const int kr2 = ks2 * 8 + (tg << 1);
#pragma unroll
            for (int dt = 0; dt < 8; dt++) {
                int dc = dt * 8 + g;
                float2 bb = *(const float2*)&sVt[dc * SVT_STRIDE + kr2];
                mma_tf32(o[dt], a0, a1, a2, a3, asu(bb.x), asu(bb.y));
            }
        }
    }

    // Epilogue: O /= l, tf32, d pair-permute (g_o feeds proj GEMM A side)
    const float il0 = 1.f / l0, il1 = 1.f / l1;
    const int b = bh >> 4, h = bh & 15;
    const int q0 = qb * 128 + w16 + g;
    float* Ob0 = g_o + ((size_t)b * N_ + q0) * DIM_ + h * 64;
    float* Ob1 = g_o + ((size_t)b * N_ + q0 + 8) * DIM_ + h * 64;
    const int j0 = qperm(tg << 1), j1 = qperm((tg << 1) + 1);
#pragma unroll
    for (int dt = 0; dt < 8; dt++) {
        Ob0[dt * 8 + j0] = f2tff(o[dt][0] * il0);
        Ob0[dt * 8 + j1] = f2tff(o[dt][1] * il0);
        Ob1[dt * 8 + j0] = f2tff(o[dt][2] * il1);
        Ob1[dt * 8 + j1] = f2tff(o[dt][3] * il1);
    }
}

// ---------------------------------------------------------------------------
// Kernel 3: output projection  g_o[8192,1024](tf32,perm) @ Wproj^T + bias
// ---------------------------------------------------------------------------
__global__ __launch_bounds__(256, 2)
void proj_gemm_kernel(const float* __restrict__ Wt, const float* __restrict__ bias,
                      float* __restrict__ out) {
    extern __shared__ float smem[];
    const int lane = threadIdx.x & 31, warp = threadIdx.x >> 5;
    const int wm = warp >> 2, wn = warp & 3;
    const int g = lane >> 2, tg = lane & 3;

    float c[4][4][4];
#pragma unroll
    for (int i = 0; i < 4; i++)
#pragma unroll
        for (int j = 0; j < 4; j++)
#pragma unroll
            for (int k = 0; k < 4; k++) c[i][j][k] = 0.f;

    gemm_tf32_128x128(g_o, DIM_, Wt, DIM_, blockIdx.y, blockIdx.x, DIM_, c, smem);

#pragma unroll
    for (int mt = 0; mt < 4; mt++)
#pragma unroll
        for (int nt = 0; nt < 4; nt++) {
            int m = blockIdx.y * 128 + wm * 64 + mt * 16 + g;
            int n = blockIdx.x * 128 + wn * 32 + nt * 8 + (tg << 1);
            float2 bb = *(const float2*)&bias[n];
            *(float2*)&out[(size_t)m * DIM_ + n] =
                make_float2(c[mt][nt][0] + bb.x, c[mt][nt][1] + bb.y);
            *(float2*)&out[(size_t)(m + 8) * DIM_ + n] =
                make_float2(c[mt][nt][2] + bb.x, c[mt][nt][3] + bb.y);
        }
}

// ---------------------------------------------------------------------------
// Launch
// ---------------------------------------------------------------------------
extern "C" void kernel_launch(void* const* d_in, const int* in_sizes, int n_in,
                              void* d_out, int out_size) {
    const float* x     = (const float*)d_in[0];
    const float* Wqkv  = (const float*)d_in[1];
    const float* Wproj = (const float*)d_in[2];
    const float* bproj = (const float*)d_in[3];
    float* out = (float*)d_out;

    const int GEMM_SMEM  = GEMM_SMEM_FLOATS * 4;    // 81920 B
    const int FLASH_SMEM = FLASH_SMEM_FLOATS * 4;   // 108544 B

    cudaFuncSetAttribute(qkv_gemm_kernel,   cudaFuncAttributeMaxDynamicSharedMemorySize, GEMM_SMEM);
    cudaFuncSetAttribute(proj_gemm_kernel,  cudaFuncAttributeMaxDynamicSharedMemorySize, GEMM_SMEM);
    cudaFuncSetAttribute(flash_attn_kernel, cudaFuncAttributeMaxDynamicSharedMemorySize, FLASH_SMEM);

    float* g_xc_p;    cudaGetSymbolAddress((void**)&g_xc_p,    g_xc);
    float* g_wqkv_p;  cudaGetSymbolAddress((void**)&g_wqkv_p,  g_wqkvt);
    float* g_wproj_p; cudaGetSymbolAddress((void**)&g_wproj_p, g_wprojt);

    // 0) one-time tf32 conversions: X pair-permuted; weights transposed+permuted
    cvt_permA_kernel<<<4096, 256>>>(x, g_xc_p, B_ * N_ * DIM_);
    cvt_transB_kernel<<<dim3(96, 32), dim3(32, 8)>>>(Wqkv,  g_wqkv_p,  DIM_, 3 * DIM_);
    cvt_transB_kernel<<<dim3(32, 32), dim3(32, 8)>>>(Wproj, g_wproj_p, DIM_, DIM_);
    // 1) QKV projection + tf32 scatter to [B,H,N,D]
    qkv_gemm_kernel<<<dim3(24, 64), 256, GEMM_SMEM>>>(g_xc_p, g_wqkv_p);
    // 1b) V transpose -> [B,H,D,N] (n pair-permuted)
    vtrans_kernel<<<dim3(64, 2, 64), dim3(32, 8)>>>();
    // 2) flash attention per (b,h)
    flash_attn_kernel<<<dim3(16, 64), 256, FLASH_SMEM>>>();
    // 3) output projection + bias
    proj_gemm_kernel<<<dim3(8, 64), 256, GEMM_SMEM>>>(g_wproj_p, bproj, out);
}